// round 1
// baseline (speedup 1.0000x reference)
#include <cuda_runtime.h>
#include <math.h>

#define B_   4
#define C_   2048
#define H_   48
#define N_   2304   /* 48*48 */
#define CAM_ 384

// ---------------- scratch (device globals: allocation-free) ----------------
__device__ float g_q  [B_ * C_ * N_];   // 75.5 MB
__device__ float g_k  [B_ * C_ * N_];   // 75.5 MB
__device__ float g_att[B_ * N_ * N_];   // 84.9 MB  (energy, then attention in-place)
__device__ float g_qn2[B_ * N_];
__device__ float g_kn2[B_ * N_];
__device__ float g_mask[B_ * N_];
__device__ double g_sum;
__device__ unsigned long long g_cnt;

// ---------------- init: zero accumulators each launch ----------------------
__global__ void init_kernel() {
    int i = blockIdx.x * blockDim.x + threadIdx.x;
    if (i < B_ * N_) { g_qn2[i] = 0.f; g_kn2[i] = 0.f; }
    if (i == 0) { g_sum = 0.0; g_cnt = 0ull; }
}

// ---------------- mask: bilinear resize (align_corners) + >0 ----------------
__global__ void mask_kernel(const float* __restrict__ cam) {
    int i = blockIdx.x * blockDim.x + threadIdx.x;
    if (i >= B_ * N_) return;
    int b = i / N_, p = i % N_;
    int oy = p / H_, ox = p % H_;
    const float step = 383.0f / 47.0f;          // (384-1)/(48-1)
    float sy = (float)oy * step;
    float sx = (float)ox * step;
    int y0 = (int)floorf(sy); y0 = max(0, min(y0, CAM_ - 1));
    int x0 = (int)floorf(sx); x0 = max(0, min(x0, CAM_ - 1));
    int y1 = min(y0 + 1, CAM_ - 1);
    int x1 = min(x0 + 1, CAM_ - 1);
    float wy = sy - (float)y0;
    float wx = sx - (float)x0;
    const float* cb = cam + (size_t)b * CAM_ * CAM_;
    float v00 = cb[y0 * CAM_ + x0]; v00 = (v00 == 255.0f) ? 0.f : v00;
    float v01 = cb[y0 * CAM_ + x1]; v01 = (v01 == 255.0f) ? 0.f : v01;
    float v10 = cb[y1 * CAM_ + x0]; v10 = (v10 == 255.0f) ? 0.f : v10;
    float v11 = cb[y1 * CAM_ + x1]; v11 = (v11 == 255.0f) ? 0.f : v11;
    float top = (1.f - wx) * v00 + wx * v01;
    float bot = (1.f - wx) * v10 + wx * v11;
    float val = (1.f - wy) * top + wy * bot;
    g_mask[i] = (val > 0.f) ? 1.f : 0.f;
}

// ---------------- generic 64x64x16 fp32 GEMM, 256 thr, 4x4 microtile -------
// AMODE 0: A is [M,K] row-major (transpose on load);  AMODE 1: A is [K,M] (direct)
// BMODE 1: B is [K,N] row-major (direct);             BMODE 0: B is [N,K] (transpose)
// EPI 0: C = acc + bias[m], store; accumulate column sum-of-squares into colnorm2
// EPI 1: C = acc, store
// EPI 2: no store; loss fusion: r = (x - gamma*acc)^2, atomics into g_sum/g_cnt
template <int AMODE, int BMODE, int EPI>
__global__ void __launch_bounds__(256)
gemm_kernel(const float* __restrict__ Ag, const float* __restrict__ Bg,
            float* __restrict__ Cg, const float* __restrict__ bias,
            const float* __restrict__ Xg, float* __restrict__ colnorm2,
            const float* __restrict__ gptr,
            int M, int Ncols, int K, int lda, int ldb, int ldc,
            long long sA, long long sB, long long sC)
{
    __shared__ float As[16][68];
    __shared__ float Bs[16][68];

    const int b  = blockIdx.z;
    const float* A = Ag + (size_t)b * sA;
    const float* Bp = Bg + (size_t)b * sB;
    const int n0 = blockIdx.x * 64;
    const int m0 = blockIdx.y * 64;
    const int tid = threadIdx.x;
    const int tx = tid & 15, ty = tid >> 4;

    float acc[4][4] = {};

    for (int kt = 0; kt < K; kt += 16) {
        if (AMODE == 0) {
            int ar = tid >> 2, ac = (tid & 3) << 2;
            float4 a4 = *(const float4*)(A + (size_t)(m0 + ar) * lda + kt + ac);
            As[ac + 0][ar] = a4.x; As[ac + 1][ar] = a4.y;
            As[ac + 2][ar] = a4.z; As[ac + 3][ar] = a4.w;
        } else {
            int ak = tid >> 4, am = (tid & 15) << 2;
            *(float4*)&As[ak][am] =
                *(const float4*)(A + (size_t)(kt + ak) * lda + m0 + am);
        }
        if (BMODE == 1) {
            int bk = tid >> 4, bn = (tid & 15) << 2;
            *(float4*)&Bs[bk][bn] =
                *(const float4*)(Bp + (size_t)(kt + bk) * ldb + n0 + bn);
        } else {
            int br = tid >> 2, bc = (tid & 3) << 2;
            float4 b4 = *(const float4*)(Bp + (size_t)(n0 + br) * ldb + kt + bc);
            Bs[bc + 0][br] = b4.x; Bs[bc + 1][br] = b4.y;
            Bs[bc + 2][br] = b4.z; Bs[bc + 3][br] = b4.w;
        }
        __syncthreads();
        #pragma unroll
        for (int kk = 0; kk < 16; kk++) {
            float4 a = *(const float4*)&As[kk][ty * 4];
            float4 v = *(const float4*)&Bs[kk][tx * 4];
            float av[4] = {a.x, a.y, a.z, a.w};
            float bv[4] = {v.x, v.y, v.z, v.w};
            #pragma unroll
            for (int i = 0; i < 4; i++)
                #pragma unroll
                for (int j = 0; j < 4; j++)
                    acc[i][j] += av[i] * bv[j];
        }
        __syncthreads();
    }

    if (EPI == 0) {
        float* Cb = Cg + (size_t)b * sC;
        float cpart[4] = {0.f, 0.f, 0.f, 0.f};
        #pragma unroll
        for (int i = 0; i < 4; i++) {
            float bv = bias[m0 + ty * 4 + i];
            #pragma unroll
            for (int j = 0; j < 4; j++) {
                float v = acc[i][j] + bv;
                Cb[(size_t)(m0 + ty * 4 + i) * ldc + n0 + tx * 4 + j] = v;
                cpart[j] += v * v;
            }
        }
        // column sum-of-squares reduce (reuse As; safe after final sync above)
        #pragma unroll
        for (int j = 0; j < 4; j++) As[ty][tx * 4 + j] = cpart[j];
        __syncthreads();
        if (tid < 64) {
            float s = 0.f;
            #pragma unroll
            for (int r = 0; r < 16; r++) s += As[r][tid];
            atomicAdd(&colnorm2[(size_t)b * Ncols + n0 + tid], s);
        }
    } else if (EPI == 1) {
        float* Cb = Cg + (size_t)b * sC;
        #pragma unroll
        for (int i = 0; i < 4; i++)
            #pragma unroll
            for (int j = 0; j < 4; j++)
                Cb[(size_t)(m0 + ty * 4 + i) * ldc + n0 + tx * 4 + j] = acc[i][j];
    } else {
        const float gm = gptr[0];
        const float* Xb = Xg + (size_t)b * sA;   // x shares A's batch stride
        float lsum = 0.f;
        unsigned lcnt = 0;
        #pragma unroll
        for (int i = 0; i < 4; i++)
            #pragma unroll
            for (int j = 0; j < 4; j++) {
                float xv = Xb[(size_t)(m0 + ty * 4 + i) * ldc + n0 + tx * 4 + j];
                float d  = xv - gm * acc[i][j];
                float rr = d * d;
                lsum += rr;
                lcnt += (rr != 0.f) ? 1u : 0u;
            }
        float*    rs = &As[0][0];
        unsigned* rc = (unsigned*)&Bs[0][0];
        rs[tid] = lsum; rc[tid] = lcnt;
        __syncthreads();
        for (int s = 128; s > 0; s >>= 1) {
            if (tid < s) { rs[tid] += rs[tid + s]; rc[tid] += rc[tid + s]; }
            __syncthreads();
        }
        if (tid == 0) {
            atomicAdd(&g_sum, (double)rs[0]);
            atomicAdd(&g_cnt, (unsigned long long)rc[0]);
        }
    }
}

// ---------------- row softmax (in-place on g_att) ---------------------------
__global__ void __launch_bounds__(256)
softmax_kernel(float* __restrict__ att)
{
    __shared__ float row[N_];
    __shared__ float red[256];
    const int n = blockIdx.x, b = blockIdx.y;
    const int tid = threadIdx.x;
    float* Ar = att + ((size_t)b * N_ + n) * N_;
    const float qs = g_qn2[b * N_ + n];

    float lmax = -INFINITY;
    for (int m = tid; m < N_; m += 256) {
        float v = Ar[m] * rsqrtf(qs * g_kn2[b * N_ + m]);
        row[m] = v;
        lmax = fmaxf(lmax, v);
    }
    red[tid] = lmax; __syncthreads();
    for (int s = 128; s > 0; s >>= 1) {
        if (tid < s) red[tid] = fmaxf(red[tid], red[tid + s]);
        __syncthreads();
    }
    float mx = red[0];
    __syncthreads();
    float lsum = 0.f;
    for (int m = tid; m < N_; m += 256) {
        float e = __expf(row[m] - mx);
        row[m] = e;
        lsum += e;
    }
    red[tid] = lsum; __syncthreads();
    for (int s = 128; s > 0; s >>= 1) {
        if (tid < s) red[tid] += red[tid + s];
        __syncthreads();
    }
    float scale = g_mask[b * N_ + n] / red[0];
    for (int m = tid; m < N_; m += 256) Ar[m] = row[m] * scale;
}

// ---------------- finalize --------------------------------------------------
__global__ void finalize_kernel(float* out) {
    out[0] = (float)(g_sum / (double)g_cnt);
}

// ---------------- launch ----------------------------------------------------
extern "C" void kernel_launch(void* const* d_in, const int* in_sizes, int n_in,
                              void* d_out, int out_size)
{
    const float* x     = (const float*)d_in[0];
    const float* cam   = (const float*)d_in[1];
    const float* Wq    = (const float*)d_in[2];
    const float* bq    = (const float*)d_in[3];
    const float* Wk    = (const float*)d_in[4];
    const float* bk    = (const float*)d_in[5];
    const float* gamma = (const float*)d_in[6];

    float *pq, *pk, *patt, *pqn2, *pkn2;
    cudaGetSymbolAddress((void**)&pq,   g_q);
    cudaGetSymbolAddress((void**)&pk,   g_k);
    cudaGetSymbolAddress((void**)&patt, g_att);
    cudaGetSymbolAddress((void**)&pqn2, g_qn2);
    cudaGetSymbolAddress((void**)&pkn2, g_kn2);

    const long long sCN = (long long)C_ * N_;
    const long long sNN = (long long)N_ * N_;

    init_kernel<<<(B_ * N_ + 255) / 256, 256>>>();
    mask_kernel<<<(B_ * N_ + 255) / 256, 256>>>(cam);

    // q = Wq * x + bq   (per batch),  fused column-norm^2
    gemm_kernel<0, 1, 0><<<dim3(N_ / 64, C_ / 64, B_), 256>>>(
        Wq, x, pq, bq, nullptr, pqn2, nullptr,
        C_, N_, C_, C_, N_, N_, 0LL, sCN, sCN);
    // k = Wk * x + bk
    gemm_kernel<0, 1, 0><<<dim3(N_ / 64, C_ / 64, B_), 256>>>(
        Wk, x, pk, bk, nullptr, pkn2, nullptr,
        C_, N_, C_, C_, N_, N_, 0LL, sCN, sCN);
    // energy = q^T k  (both [C, N] k-major -> direct loads)
    gemm_kernel<1, 1, 1><<<dim3(N_ / 64, N_ / 64, B_), 256>>>(
        pq, pk, patt, nullptr, nullptr, nullptr, nullptr,
        N_, N_, C_, N_, N_, N_, sCN, sCN, sNN);
    // softmax(energy / (|q||k|)) * mask, in place
    softmax_kernel<<<dim3(N_, B_), 256>>>(patt);
    // new_x = x * atten^T, fused loss: sum (x - gamma*new_x)^2 and nonzero count
    gemm_kernel<0, 0, 2><<<dim3(N_ / 64, C_ / 64, B_), 256>>>(
        x, patt, nullptr, nullptr, x, nullptr, gamma,
        C_, N_, N_, N_, N_, N_, sCN, sNN, 0LL);

    finalize_kernel<<<1, 1>>>((float*)d_out);
}